// round 13
// baseline (speedup 1.0000x reference)
#include <cuda_runtime.h>
#include <cuda_fp16.h>
#include <math.h>

#define FR 16
#define NV 4096
#define NT 512
#define MP 4096
#define SCALE 0.1f

#define CHUNKS 8
#define CHUNK_PTS (MP / CHUNKS)        // 512 model points per chunk
#define CHUNK_PAIRS (CHUNK_PTS / 2)    // 256 pair records
#define P 8                            // pred points per thread (consecutive)
#define TPB 256
#define TILE_PTS (TPB * P)             // 2048 pred points per tile
#define TOTAL_PTS (FR * NV + FR * NT)  // 73728
#define N_TILES (TOTAL_PTS / TILE_PTS) // 36

__device__ float g_partial[CHUNKS][TOTAL_PTS];
__device__ float g_tilesum[N_TILES];
__device__ int   g_ttk[N_TILES];       // per-tile tickets (zero-init, reset each run)
__device__ int   g_gtk;                // global ticket

__device__ __forceinline__ void rot_from_omega(float ox, float oy, float oz,
                                               float dtv, float* R) {
    float th = sqrtf(ox*ox + oy*oy + oz*oz);
    float inv = 1.0f / fmaxf(th, 1e-8f);
    float ax = ox*inv, ay = oy*inv, az = oz*inv;
    float s = sinf(th * dtv);
    float c = 1.0f - cosf(th * dtv);
    float S[9] = {0.f, -az, ay,  az, 0.f, -ax,  -ay, ax, 0.f};
    float S2[9];
    #pragma unroll
    for (int i = 0; i < 3; i++)
        #pragma unroll
        for (int j = 0; j < 3; j++) {
            float v = 0.f;
            #pragma unroll
            for (int k = 0; k < 3; k++) v += S[i*3+k] * S[k*3+j];
            S2[i*3+j] = v;
        }
    #pragma unroll
    for (int i = 0; i < 9; i++) {
        float eye = (i == 0 || i == 4 || i == 8) ? 1.0f : 0.0f;
        R[i] = eye + s * S[i] + c * S2[i];
    }
}

__global__ void __launch_bounds__(TPB, 2)
chamfer_kernel(const float* __restrict__ state,
               const float* __restrict__ pps,
               const float* __restrict__ dt,
               const float* __restrict__ model,
               const float* __restrict__ vis,
               const float* __restrict__ tac,
               float* __restrict__ out) {
    // smem: one 16B record per 2 model points, all half2:
    // [x0x1 | y0y1 | z0z1 | n0n1]  -> single LDS.128 per pair
    __shared__ __align__(16) __half2 sh[CHUNK_PAIRS * 4];   // 4 KB
    __shared__ float sA[FR][9];
    __shared__ float sB[FR][3];
    __shared__ float xR[FR][9];
    __shared__ float xT[FR][3];
    __shared__ float warp_sums[8];
    __shared__ int   role;              // 0 = done, 1 = tile finisher, 2 = global

    const int tid = threadIdx.x;
    const int tile = blockIdx.x;
    const int chunk = blockIdx.y;
    const int tileBase = tile * TILE_PTS;

    // ---- Stage model chunk as fp16 pair records ----
    if (tid < CHUNK_PAIRS) {
        int j = tid;
        int m0 = chunk * CHUNK_PTS + 2 * j;
        float x0 = model[3*m0+0], y0 = model[3*m0+1], z0 = model[3*m0+2];
        float x1 = model[3*m0+3], y1 = model[3*m0+4], z1 = model[3*m0+5];
        __half2* sp = sh + 4 * j;
        sp[0] = __floats2half2_rn(x0, x1);
        sp[1] = __floats2half2_rn(y0, y1);
        sp[2] = __floats2half2_rn(z0, z1);
        sp[3] = __floats2half2_rn(x0*x0 + y0*y0 + z0*z0,
                                  x1*x1 + y1*y1 + z1*z1);
    }

    // ---- Pose: warp 0, thread f owns frame f; Hillis-Steele scan ----
    if (tid < 32) {
        const int f = tid;
        float r[9], tv[3];
        if (f < FR) {
            if (f == 0) {
                rot_from_omega(state[3], state[4], state[5], 1.0f, r);
                tv[0] = state[0]; tv[1] = state[1]; tv[2] = state[2];
            } else {
                const float* row = pps + f * 12;
                float d = dt[f];
                rot_from_omega(row[9], row[10], row[11], d, r);
                tv[0] = row[6] * d; tv[1] = row[7] * d; tv[2] = row[8] * d;
            }
        }
        #pragma unroll
        for (int d = 1; d < FR; d <<= 1) {
            if (f < FR) {
                #pragma unroll
                for (int i = 0; i < 9; i++) xR[f][i] = r[i];
                #pragma unroll
                for (int i = 0; i < 3; i++) xT[f][i] = tv[i];
            }
            __syncwarp();
            float pR[9], pT[3];
            if (f < FR && f >= d) {
                #pragma unroll
                for (int i = 0; i < 9; i++) pR[i] = xR[f-d][i];
                #pragma unroll
                for (int i = 0; i < 3; i++) pT[i] = xT[f-d][i];
            }
            __syncwarp();
            if (f < FR && f >= d) {
                float rn[9];
                #pragma unroll
                for (int i = 0; i < 3; i++)
                    #pragma unroll
                    for (int j = 0; j < 3; j++)
                        rn[i*3+j] = r[i*3+0]*pR[0*3+j] + r[i*3+1]*pR[1*3+j]
                                  + r[i*3+2]*pR[2*3+j];
                #pragma unroll
                for (int i = 0; i < 9; i++) r[i] = rn[i];
                #pragma unroll
                for (int i = 0; i < 3; i++) tv[i] += pT[i];
            }
        }
        if (f < FR) {
            const float invS = 1.0f / SCALE;
            #pragma unroll
            for (int i = 0; i < 9; i++) sA[f][i] = r[i] * invS;
            #pragma unroll
            for (int j = 0; j < 3; j++) {
                float v = tv[0]*r[0*3+j] + tv[1]*r[1*3+j] + tv[2]*r[2*3+j];
                sB[f][j] = -v * invS;
            }
        }
    }
    __syncthreads();

    // ---- Per-thread setup: 8 consecutive pred points ----
    const int idx0 = tileBase + tid * P;
    int f;
    const float* pbase;
    if (idx0 < FR * NV) {
        f = idx0 >> 12;
        pbase = vis + 3 * idx0;
    } else {
        int j = idx0 - FR * NV;
        f = j >> 9;
        pbase = tac + 3 * j;
    }

    float pc[24];
    {
        const float4* pv = (const float4*)pbase;   // 16B-aligned (idx0 % 8 == 0)
        #pragma unroll
        for (int i = 0; i < 6; i++) {
            float4 q = pv[i];
            pc[4*i+0] = q.x; pc[4*i+1] = q.y; pc[4*i+2] = q.z; pc[4*i+3] = q.w;
        }
    }

    __half2 mxx[P], myy[P], mzz[P], bb[P];
    float pn[P];
    {
        const float* A = sA[f];
        const float* B = sB[f];
        const __half2 binit = __floats2half2_rn(65504.f, 65504.f);
        #pragma unroll
        for (int k = 0; k < P; k++) {
            float px = pc[3*k], py = pc[3*k+1], pz = pc[3*k+2];
            float cx = fmaf(px, A[0], fmaf(py, A[3], fmaf(pz, A[6], B[0])));
            float cy = fmaf(px, A[1], fmaf(py, A[4], fmaf(pz, A[7], B[1])));
            float cz = fmaf(px, A[2], fmaf(py, A[5], fmaf(pz, A[8], B[2])));
            pn[k] = cx*cx + cy*cy + cz*cz;
            mxx[k] = __float2half2_rn(-2.0f * cx);
            myy[k] = __float2half2_rn(-2.0f * cy);
            mzz[k] = __float2half2_rn(-2.0f * cz);
            bb[k] = binit;
        }
    }

    // ---- Main loop: fp16x2 FMA + fp16x2 MIN, one LDS.128 per pair ----
    const uint4* sp4 = (const uint4*)sh;
    #pragma unroll 4
    for (int j = 0; j < CHUNK_PAIRS; j++) {
        uint4 v = sp4[j];
        __half2 x01 = *reinterpret_cast<__half2*>(&v.x);
        __half2 y01 = *reinterpret_cast<__half2*>(&v.y);
        __half2 z01 = *reinterpret_cast<__half2*>(&v.z);
        __half2 n01 = *reinterpret_cast<__half2*>(&v.w);
        #pragma unroll
        for (int k = 0; k < P; k++) {
            __half2 acc = __hfma2(mzz[k], z01, n01);
            acc = __hfma2(myy[k], y01, acc);
            acc = __hfma2(mxx[k], x01, acc);
            bb[k] = __hmin2(bb[k], acc);
        }
    }

    // ---- Write 8 consecutive partials (pn added back in fp32) ----
    float res[P];
    #pragma unroll
    for (int k = 0; k < P; k++) {
        float lo = __low2float(bb[k]);
        float hi = __high2float(bb[k]);
        res[k] = pn[k] + fminf(lo, hi);
    }
    float4* dst = (float4*)&g_partial[chunk][idx0];
    dst[0] = make_float4(res[0], res[1], res[2], res[3]);
    dst[1] = make_float4(res[4], res[5], res[6], res[7]);

    // ---- Tile ticket: last chunk-block of this tile combines ----
    __syncthreads();
    if (tid == 0) {
        __threadfence();
        int t = atomicAdd(&g_ttk[tile], 1);
        role = (t == CHUNKS - 1) ? 1 : 0;
    }
    __syncthreads();

    unsigned mask = 0xFFFFFFFFu;
    if (role == 1) {
        __threadfence();
        const float w = (tileBase < FR * NV) ? (1.0f / (float)NV)
                                             : (0.1f / (float)NT);
        const int base = tileBase + tid * P;
        float4 a0 = *(const float4*)&g_partial[0][base];
        float4 a1 = *(const float4*)&g_partial[0][base + 4];
        #pragma unroll
        for (int c = 1; c < CHUNKS; c++) {
            float4 b0 = *(const float4*)&g_partial[c][base];
            float4 b1 = *(const float4*)&g_partial[c][base + 4];
            a0.x = fminf(a0.x, b0.x); a0.y = fminf(a0.y, b0.y);
            a0.z = fminf(a0.z, b0.z); a0.w = fminf(a0.w, b0.w);
            a1.x = fminf(a1.x, b1.x); a1.y = fminf(a1.y, b1.y);
            a1.z = fminf(a1.z, b1.z); a1.w = fminf(a1.w, b1.w);
        }
        float contrib = ((a0.x + a0.y) + (a0.z + a0.w)
                       + (a1.x + a1.y) + (a1.z + a1.w)) * w;
        #pragma unroll
        for (int off = 16; off > 0; off >>= 1)
            contrib += __shfl_down_sync(mask, contrib, off);
        int lane = tid & 31, wid = tid >> 5;
        if (lane == 0) warp_sums[wid] = contrib;
        __syncthreads();
        if (tid == 0) {
            float v = 0.0f;
            #pragma unroll
            for (int i = 0; i < 8; i++) v += warp_sums[i];
            g_tilesum[tile] = v;
            __threadfence();
            int t = atomicAdd(&g_gtk, 1);
            role = (t == N_TILES - 1) ? 2 : 0;
        }
        __syncthreads();
    }

    // ---- Global finisher: sum tile sums, write out, reset tickets ----
    if (role == 2) {
        __threadfence();
        float v = (tid < N_TILES) ? g_tilesum[tid] : 0.0f;
        #pragma unroll
        for (int off = 16; off > 0; off >>= 1)
            v += __shfl_down_sync(mask, v, off);
        int lane = tid & 31, wid = tid >> 5;
        if (lane == 0) warp_sums[wid] = v;
        __syncthreads();
        if (tid < N_TILES) g_ttk[tid] = 0;        // reset for next replay
        if (tid == 0) {
            out[0] = warp_sums[0] + warp_sums[1];  // N_TILES=36 -> warps 0,1
            g_gtk = 0;
        }
    }
}

extern "C" void kernel_launch(void* const* d_in, const int* in_sizes, int n_in,
                              void* d_out, int out_size) {
    const float* state = (const float*)d_in[0];
    const float* model = (const float*)d_in[1];
    const float* vis   = (const float*)d_in[2];
    const float* tac   = (const float*)d_in[3];
    const float* pps   = (const float*)d_in[4];
    const float* dt    = (const float*)d_in[5];
    float* out = (float*)d_out;

    dim3 grid(N_TILES, CHUNKS);   // 36 x 8 = 288 blocks, 2 per SM
    chamfer_kernel<<<grid, TPB>>>(state, pps, dt, model, vis, tac, out);
}

// round 15
// speedup vs baseline: 1.1141x; 1.1141x over previous
#include <cuda_runtime.h>
#include <math.h>

#define FR 16
#define NV 4096
#define NT 512
#define MP 4096
#define SCALE 0.1f

#define CHUNKS 12
#define CHUNK_PTS 342                  // ceil(4096/12); last chunk padded
#define P 8                            // pred points per thread (consecutive)
#define TPB 256
#define TILE_PTS (TPB * P)             // 2048 pred points per tile
#define TOTAL_PTS (FR * NV + FR * NT)  // 73728
#define N_TILES (TOTAL_PTS / TILE_PTS) // 36

__device__ float g_partial[CHUNKS][TOTAL_PTS];
__device__ float g_tilesum[N_TILES];
__device__ int   g_ttk[N_TILES];       // per-tile tickets (zero-init, reset each run)
__device__ int   g_gtk;                // global ticket

typedef unsigned long long u64;

__device__ __forceinline__ u64 pack2(float a, float b) {
    u64 r;
    asm("mov.b64 %0, {%1, %2};" : "=l"(r) : "f"(a), "f"(b));
    return r;
}
__device__ __forceinline__ void unpack2(u64 v, float& a, float& b) {
    asm("mov.b64 {%0, %1}, %2;" : "=f"(a), "=f"(b) : "l"(v));
}
#define FMA2(d, a, b, c) \
    asm("fma.rn.f32x2 %0, %1, %2, %3;" : "=l"(d) : "l"(a), "l"(b), "l"(c))

__device__ __forceinline__ void rot_from_omega(float ox, float oy, float oz,
                                               float dtv, float* R) {
    float th = sqrtf(ox*ox + oy*oy + oz*oz);
    float inv = 1.0f / fmaxf(th, 1e-8f);
    float ax = ox*inv, ay = oy*inv, az = oz*inv;
    float s = sinf(th * dtv);
    float c = 1.0f - cosf(th * dtv);
    float S[9] = {0.f, -az, ay,  az, 0.f, -ax,  -ay, ax, 0.f};
    float S2[9];
    #pragma unroll
    for (int i = 0; i < 3; i++)
        #pragma unroll
        for (int j = 0; j < 3; j++) {
            float v = 0.f;
            #pragma unroll
            for (int k = 0; k < 3; k++) v += S[i*3+k] * S[k*3+j];
            S2[i*3+j] = v;
        }
    #pragma unroll
    for (int i = 0; i < 9; i++) {
        float eye = (i == 0 || i == 4 || i == 8) ? 1.0f : 0.0f;
        R[i] = eye + s * S[i] + c * S2[i];
    }
}

__global__ void __launch_bounds__(TPB, 3)
chamfer_kernel(const float* __restrict__ state,
               const float* __restrict__ pps,
               const float* __restrict__ dt,
               const float* __restrict__ model,
               const float* __restrict__ vis,
               const float* __restrict__ tac,
               float* __restrict__ out) {
    // smem: 32B per model point, dup-packed f32x2 halves:
    // [(x,x) | (y,y)] [(z,z) | (n,n)]  -> two ulonglong2 loads per point
    __shared__ __align__(16) ulonglong2 s2[CHUNK_PTS * 2];   // ~10.9 KB
    __shared__ float sA[FR][9];
    __shared__ float sB[FR][3];
    __shared__ float xR[FR][9];
    __shared__ float xT[FR][3];
    __shared__ float warp_sums[8];
    __shared__ int   role;              // 0 = done, 1 = tile finisher, 2 = global

    const int tid = threadIdx.x;
    const int tile = blockIdx.x;
    const int chunk = blockIdx.y;
    const int tileBase = tile * TILE_PTS;

    // ---- Stage model chunk, dup-packed; pad out-of-range with far point ----
    for (int j = tid; j < CHUNK_PTS; j += TPB) {
        int m = chunk * CHUNK_PTS + j;
        float x, y, z;
        if (m < MP) {
            x = model[3*m+0]; y = model[3*m+1]; z = model[3*m+2];
        } else {
            x = 1.0e4f; y = 1.0e4f; z = 1.0e4f;   // never the min
        }
        float n = x*x + y*y + z*z;
        s2[2*j]   = make_ulonglong2(pack2(x, x), pack2(y, y));
        s2[2*j+1] = make_ulonglong2(pack2(z, z), pack2(n, n));
    }

    // ---- Pose: warp 0, thread f owns frame f; Hillis-Steele scan ----
    if (tid < 32) {
        const int f = tid;
        float r[9], tv[3];
        if (f < FR) {
            if (f == 0) {
                rot_from_omega(state[3], state[4], state[5], 1.0f, r);
                tv[0] = state[0]; tv[1] = state[1]; tv[2] = state[2];
            } else {
                const float* row = pps + f * 12;
                float d = dt[f];
                rot_from_omega(row[9], row[10], row[11], d, r);
                tv[0] = row[6] * d; tv[1] = row[7] * d; tv[2] = row[8] * d;
            }
        }
        #pragma unroll
        for (int d = 1; d < FR; d <<= 1) {
            if (f < FR) {
                #pragma unroll
                for (int i = 0; i < 9; i++) xR[f][i] = r[i];
                #pragma unroll
                for (int i = 0; i < 3; i++) xT[f][i] = tv[i];
            }
            __syncwarp();
            float pR[9], pT[3];
            if (f < FR && f >= d) {
                #pragma unroll
                for (int i = 0; i < 9; i++) pR[i] = xR[f-d][i];
                #pragma unroll
                for (int i = 0; i < 3; i++) pT[i] = xT[f-d][i];
            }
            __syncwarp();
            if (f < FR && f >= d) {
                float rn[9];
                #pragma unroll
                for (int i = 0; i < 3; i++)
                    #pragma unroll
                    for (int j = 0; j < 3; j++)
                        rn[i*3+j] = r[i*3+0]*pR[0*3+j] + r[i*3+1]*pR[1*3+j]
                                  + r[i*3+2]*pR[2*3+j];
                #pragma unroll
                for (int i = 0; i < 9; i++) r[i] = rn[i];
                #pragma unroll
                for (int i = 0; i < 3; i++) tv[i] += pT[i];
            }
        }
        if (f < FR) {
            const float invS = 1.0f / SCALE;
            #pragma unroll
            for (int i = 0; i < 9; i++) sA[f][i] = r[i] * invS;
            #pragma unroll
            for (int j = 0; j < 3; j++) {
                float v = tv[0]*r[0*3+j] + tv[1]*r[1*3+j] + tv[2]*r[2*3+j];
                sB[f][j] = -v * invS;
            }
        }
    }
    __syncthreads();

    // ---- Per-thread setup: 8 consecutive pred points ----
    const int idx0 = tileBase + tid * P;
    int f;
    const float* pbase;
    if (idx0 < FR * NV) {
        f = idx0 >> 12;
        pbase = vis + 3 * idx0;
    } else {
        int j = idx0 - FR * NV;
        f = j >> 9;
        pbase = tac + 3 * j;
    }

    float pc[24];
    {
        const float4* pv = (const float4*)pbase;   // 16B-aligned (idx0 % 8 == 0)
        #pragma unroll
        for (int i = 0; i < 6; i++) {
            float4 q = pv[i];
            pc[4*i+0] = q.x; pc[4*i+1] = q.y; pc[4*i+2] = q.z; pc[4*i+3] = q.w;
        }
    }

    // Pack pairs of DIFFERENT preds per f32x2 lane: 12 u64 multipliers total
    u64 cxp[4], cyp[4], czp[4];
    float pn[P], bl[4], bh[4];
    {
        const float* A = sA[f];
        const float* B = sB[f];
        float mx[P], my[P], mz[P];
        #pragma unroll
        for (int k = 0; k < P; k++) {
            float px = pc[3*k], py = pc[3*k+1], pz = pc[3*k+2];
            float cx = fmaf(px, A[0], fmaf(py, A[3], fmaf(pz, A[6], B[0])));
            float cy = fmaf(px, A[1], fmaf(py, A[4], fmaf(pz, A[7], B[1])));
            float cz = fmaf(px, A[2], fmaf(py, A[5], fmaf(pz, A[8], B[2])));
            pn[k] = cx*cx + cy*cy + cz*cz;
            mx[k] = -2.0f * cx; my[k] = -2.0f * cy; mz[k] = -2.0f * cz;
        }
        #pragma unroll
        for (int p = 0; p < 4; p++) {
            cxp[p] = pack2(mx[2*p], mx[2*p+1]);
            cyp[p] = pack2(my[2*p], my[2*p+1]);
            czp[p] = pack2(mz[2*p], mz[2*p+1]);
            bl[p] = INFINITY;
            bh[p] = INFINITY;
        }
    }

    // ---- Main loop: 1 model point/iter; lanes = 2 different preds ----
    #pragma unroll 2
    for (int j = 0; j < CHUNK_PTS; j++) {
        ulonglong2 a = s2[2*j];        // .x = (x,x)  .y = (y,y)
        ulonglong2 b = s2[2*j+1];      // .x = (z,z)  .y = (n,n)
        #pragma unroll
        for (int p = 0; p < 4; p++) {
            u64 acc;
            FMA2(acc, czp[p], b.x, b.y);
            FMA2(acc, cyp[p], a.y, acc);
            FMA2(acc, cxp[p], a.x, acc);
            float lo, hi;
            unpack2(acc, lo, hi);
            bl[p] = fminf(bl[p], lo);   // pred 2p
            bh[p] = fminf(bh[p], hi);   // pred 2p+1
        }
    }

    // ---- Write 8 consecutive partials ----
    float res[P];
    #pragma unroll
    for (int p = 0; p < 4; p++) {
        res[2*p]   = pn[2*p]   + bl[p];
        res[2*p+1] = pn[2*p+1] + bh[p];
    }
    float4* dst = (float4*)&g_partial[chunk][idx0];
    dst[0] = make_float4(res[0], res[1], res[2], res[3]);
    dst[1] = make_float4(res[4], res[5], res[6], res[7]);

    // ---- Tile ticket: last chunk-block of this tile combines ----
    __syncthreads();
    if (tid == 0) {
        __threadfence();
        int t = atomicAdd(&g_ttk[tile], 1);
        role = (t == CHUNKS - 1) ? 1 : 0;
    }
    __syncthreads();

    unsigned mask = 0xFFFFFFFFu;
    if (role == 1) {
        __threadfence();
        const float w = (tileBase < FR * NV) ? (1.0f / (float)NV)
                                             : (0.1f / (float)NT);
        const int base = tileBase + tid * P;
        float4 a0 = *(const float4*)&g_partial[0][base];
        float4 a1 = *(const float4*)&g_partial[0][base + 4];
        #pragma unroll
        for (int c = 1; c < CHUNKS; c++) {
            float4 b0 = *(const float4*)&g_partial[c][base];
            float4 b1 = *(const float4*)&g_partial[c][base + 4];
            a0.x = fminf(a0.x, b0.x); a0.y = fminf(a0.y, b0.y);
            a0.z = fminf(a0.z, b0.z); a0.w = fminf(a0.w, b0.w);
            a1.x = fminf(a1.x, b1.x); a1.y = fminf(a1.y, b1.y);
            a1.z = fminf(a1.z, b1.z); a1.w = fminf(a1.w, b1.w);
        }
        float contrib = ((a0.x + a0.y) + (a0.z + a0.w)
                       + (a1.x + a1.y) + (a1.z + a1.w)) * w;
        #pragma unroll
        for (int off = 16; off > 0; off >>= 1)
            contrib += __shfl_down_sync(mask, contrib, off);
        int lane = tid & 31, wid = tid >> 5;
        if (lane == 0) warp_sums[wid] = contrib;
        __syncthreads();
        if (tid == 0) {
            float v = 0.0f;
            #pragma unroll
            for (int i = 0; i < 8; i++) v += warp_sums[i];
            g_tilesum[tile] = v;
            __threadfence();
            int t = atomicAdd(&g_gtk, 1);
            role = (t == N_TILES - 1) ? 2 : 0;
        }
        __syncthreads();
    }

    // ---- Global finisher: sum tile sums, write out, reset tickets ----
    if (role == 2) {
        __threadfence();
        float v = (tid < N_TILES) ? g_tilesum[tid] : 0.0f;
        #pragma unroll
        for (int off = 16; off > 0; off >>= 1)
            v += __shfl_down_sync(mask, v, off);
        int lane = tid & 31, wid = tid >> 5;
        if (lane == 0) warp_sums[wid] = v;
        __syncthreads();
        if (tid < N_TILES) g_ttk[tid] = 0;        // reset for next replay
        if (tid == 0) {
            out[0] = warp_sums[0] + warp_sums[1];  // N_TILES=36 -> warps 0,1
            g_gtk = 0;
        }
    }
}

extern "C" void kernel_launch(void* const* d_in, const int* in_sizes, int n_in,
                              void* d_out, int out_size) {
    const float* state = (const float*)d_in[0];
    const float* model = (const float*)d_in[1];
    const float* vis   = (const float*)d_in[2];
    const float* tac   = (const float*)d_in[3];
    const float* pps   = (const float*)d_in[4];
    const float* dt    = (const float*)d_in[5];
    float* out = (float*)d_out;

    dim3 grid(N_TILES, CHUNKS);   // 36 x 12 = 432 blocks, ~3 per SM
    chamfer_kernel<<<grid, TPB>>>(state, pps, dt, model, vis, tac, out);
}

// round 16
// speedup vs baseline: 1.5797x; 1.4179x over previous
#include <cuda_runtime.h>
#include <cuda_fp16.h>
#include <math.h>

#define FR 16
#define NV 4096
#define NT 512
#define MP 4096
#define SCALE 0.1f
#define BIAS 576.0f

#define CHUNKS 16
#define CHUNK_PTS (MP / CHUNKS)        // 256 model points per chunk
#define CHUNK_PAIRS (CHUNK_PTS / 2)    // 128 pair records
#define P 8                            // pred points per thread (consecutive)
#define TPB 256
#define TILE_PTS (TPB * P)             // 2048 pred points per tile
#define TOTAL_PTS (FR * NV + FR * NT)  // 73728
#define N_TILES (TOTAL_PTS / TILE_PTS) // 36

__device__ float g_partial[CHUNKS][TOTAL_PTS];
__device__ float g_tilesum[N_TILES];
__device__ int   g_ttk[N_TILES];       // per-tile tickets (zero-init, reset each run)
__device__ int   g_gtk;                // global ticket

#define MINU16X2(d, a, b) \
    asm("min.u16x2 %0, %1, %2;" : "=r"(d) : "r"(a), "r"(b))

__device__ __forceinline__ void rot_from_omega(float ox, float oy, float oz,
                                               float dtv, float* R) {
    float th = sqrtf(ox*ox + oy*oy + oz*oz);
    float inv = 1.0f / fmaxf(th, 1e-8f);
    float ax = ox*inv, ay = oy*inv, az = oz*inv;
    float s = sinf(th * dtv);
    float c = 1.0f - cosf(th * dtv);
    float S[9] = {0.f, -az, ay,  az, 0.f, -ax,  -ay, ax, 0.f};
    float S2[9];
    #pragma unroll
    for (int i = 0; i < 3; i++)
        #pragma unroll
        for (int j = 0; j < 3; j++) {
            float v = 0.f;
            #pragma unroll
            for (int k = 0; k < 3; k++) v += S[i*3+k] * S[k*3+j];
            S2[i*3+j] = v;
        }
    #pragma unroll
    for (int i = 0; i < 9; i++) {
        float eye = (i == 0 || i == 4 || i == 8) ? 1.0f : 0.0f;
        R[i] = eye + s * S[i] + c * S2[i];
    }
}

__global__ void __launch_bounds__(TPB, 4)
chamfer_kernel(const float* __restrict__ state,
               const float* __restrict__ pps,
               const float* __restrict__ dt,
               const float* __restrict__ model,
               const float* __restrict__ vis,
               const float* __restrict__ tac,
               float* __restrict__ out) {
    // smem: 16B fp16 record per 2 model points: [x0x1|y0y1|z0z1|(n+BIAS)01]
    __shared__ __align__(16) __half2 sh[CHUNK_PAIRS * 4];   // 2 KB
    __shared__ float sA[FR][9];
    __shared__ float sB[FR][3];
    __shared__ float xR[FR][9];
    __shared__ float xT[FR][3];
    __shared__ float warp_sums[8];
    __shared__ int   role;              // 0 = done, 1 = tile finisher, 2 = global

    const int tid = threadIdx.x;
    const int tile = blockIdx.x;
    const int chunk = blockIdx.y;
    const int tileBase = tile * TILE_PTS;

    // ---- Stage model chunk as biased fp16 pair records ----
    if (tid < CHUNK_PAIRS) {
        int j = tid;
        int m0 = chunk * CHUNK_PTS + 2 * j;
        float x0 = model[3*m0+0], y0 = model[3*m0+1], z0 = model[3*m0+2];
        float x1 = model[3*m0+3], y1 = model[3*m0+4], z1 = model[3*m0+5];
        __half2* sp = sh + 4 * j;
        sp[0] = __floats2half2_rn(x0, x1);
        sp[1] = __floats2half2_rn(y0, y1);
        sp[2] = __floats2half2_rn(z0, z1);
        sp[3] = __floats2half2_rn(x0*x0 + y0*y0 + z0*z0 + BIAS,
                                  x1*x1 + y1*y1 + z1*z1 + BIAS);
    }

    // ---- Pose: warp 0, thread f owns frame f; Hillis-Steele scan ----
    if (tid < 32) {
        const int f = tid;
        float r[9], tv[3];
        if (f < FR) {
            if (f == 0) {
                rot_from_omega(state[3], state[4], state[5], 1.0f, r);
                tv[0] = state[0]; tv[1] = state[1]; tv[2] = state[2];
            } else {
                const float* row = pps + f * 12;
                float d = dt[f];
                rot_from_omega(row[9], row[10], row[11], d, r);
                tv[0] = row[6] * d; tv[1] = row[7] * d; tv[2] = row[8] * d;
            }
        }
        #pragma unroll
        for (int d = 1; d < FR; d <<= 1) {
            if (f < FR) {
                #pragma unroll
                for (int i = 0; i < 9; i++) xR[f][i] = r[i];
                #pragma unroll
                for (int i = 0; i < 3; i++) xT[f][i] = tv[i];
            }
            __syncwarp();
            float pR[9], pT[3];
            if (f < FR && f >= d) {
                #pragma unroll
                for (int i = 0; i < 9; i++) pR[i] = xR[f-d][i];
                #pragma unroll
                for (int i = 0; i < 3; i++) pT[i] = xT[f-d][i];
            }
            __syncwarp();
            if (f < FR && f >= d) {
                float rn[9];
                #pragma unroll
                for (int i = 0; i < 3; i++)
                    #pragma unroll
                    for (int j = 0; j < 3; j++)
                        rn[i*3+j] = r[i*3+0]*pR[0*3+j] + r[i*3+1]*pR[1*3+j]
                                  + r[i*3+2]*pR[2*3+j];
                #pragma unroll
                for (int i = 0; i < 9; i++) r[i] = rn[i];
                #pragma unroll
                for (int i = 0; i < 3; i++) tv[i] += pT[i];
            }
        }
        if (f < FR) {
            const float invS = 1.0f / SCALE;
            #pragma unroll
            for (int i = 0; i < 9; i++) sA[f][i] = r[i] * invS;
            #pragma unroll
            for (int j = 0; j < 3; j++) {
                float v = tv[0]*r[0*3+j] + tv[1]*r[1*3+j] + tv[2]*r[2*3+j];
                sB[f][j] = -v * invS;
            }
        }
    }
    __syncthreads();

    // ---- Per-thread setup: 8 consecutive pred points ----
    const int idx0 = tileBase + tid * P;
    int f;
    const float* pbase;
    if (idx0 < FR * NV) {
        f = idx0 >> 12;
        pbase = vis + 3 * idx0;
    } else {
        int j = idx0 - FR * NV;
        f = j >> 9;
        pbase = tac + 3 * j;
    }

    float pc[24];
    {
        const float4* pv = (const float4*)pbase;   // 16B-aligned (idx0 % 8 == 0)
        #pragma unroll
        for (int i = 0; i < 6; i++) {
            float4 q = pv[i];
            pc[4*i+0] = q.x; pc[4*i+1] = q.y; pc[4*i+2] = q.z; pc[4*i+3] = q.w;
        }
    }

    __half2 mxx[P], myy[P], mzz[P];
    unsigned bb[P];
    float pn[P];
    {
        const float* A = sA[f];
        const float* B = sB[f];
        #pragma unroll
        for (int k = 0; k < P; k++) {
            float px = pc[3*k], py = pc[3*k+1], pz = pc[3*k+2];
            float cx = fmaf(px, A[0], fmaf(py, A[3], fmaf(pz, A[6], B[0])));
            float cy = fmaf(px, A[1], fmaf(py, A[4], fmaf(pz, A[7], B[1])));
            float cz = fmaf(px, A[2], fmaf(py, A[5], fmaf(pz, A[8], B[2])));
            pn[k] = cx*cx + cy*cy + cz*cz;
            mxx[k] = __float2half2_rn(-2.0f * cx);
            myy[k] = __float2half2_rn(-2.0f * cy);
            mzz[k] = __float2half2_rn(-2.0f * cz);
            bb[k] = 0x7BFF7BFFu;        // (65504, 65504) fp16 — max finite
        }
    }

    // ---- Main loop: 3 HFMA2 + 1 min.u16x2 per 2 model points per pred ----
    const uint4* sp4 = (const uint4*)sh;
    #pragma unroll 4
    for (int j = 0; j < CHUNK_PAIRS; j++) {
        uint4 v = sp4[j];
        __half2 x01 = *reinterpret_cast<__half2*>(&v.x);
        __half2 y01 = *reinterpret_cast<__half2*>(&v.y);
        __half2 z01 = *reinterpret_cast<__half2*>(&v.z);
        __half2 n01 = *reinterpret_cast<__half2*>(&v.w);
        #pragma unroll
        for (int k = 0; k < P; k++) {
            __half2 acc = __hfma2(mzz[k], z01, n01);
            acc = __hfma2(myy[k], y01, acc);
            acc = __hfma2(mxx[k], x01, acc);
            unsigned au = *reinterpret_cast<unsigned*>(&acc);
            MINU16X2(bb[k], bb[k], au);   // positive fp16: uint order == fp order
        }
    }

    // ---- Write 8 consecutive partials (un-bias in fp32) ----
    float res[P];
    #pragma unroll
    for (int k = 0; k < P; k++) {
        __half2 b2 = *reinterpret_cast<__half2*>(&bb[k]);
        float lo = __low2float(b2);
        float hi = __high2float(b2);
        res[k] = pn[k] + (fminf(lo, hi) - BIAS);
    }
    float4* dst = (float4*)&g_partial[chunk][idx0];
    dst[0] = make_float4(res[0], res[1], res[2], res[3]);
    dst[1] = make_float4(res[4], res[5], res[6], res[7]);

    // ---- Tile ticket: last chunk-block of this tile combines ----
    __syncthreads();
    if (tid == 0) {
        __threadfence();
        int t = atomicAdd(&g_ttk[tile], 1);
        role = (t == CHUNKS - 1) ? 1 : 0;
    }
    __syncthreads();

    unsigned mask = 0xFFFFFFFFu;
    if (role == 1) {
        __threadfence();
        const float w = (tileBase < FR * NV) ? (1.0f / (float)NV)
                                             : (0.1f / (float)NT);
        const int base = tileBase + tid * P;
        float4 a0 = *(const float4*)&g_partial[0][base];
        float4 a1 = *(const float4*)&g_partial[0][base + 4];
        #pragma unroll
        for (int c = 1; c < CHUNKS; c++) {
            float4 b0 = *(const float4*)&g_partial[c][base];
            float4 b1 = *(const float4*)&g_partial[c][base + 4];
            a0.x = fminf(a0.x, b0.x); a0.y = fminf(a0.y, b0.y);
            a0.z = fminf(a0.z, b0.z); a0.w = fminf(a0.w, b0.w);
            a1.x = fminf(a1.x, b1.x); a1.y = fminf(a1.y, b1.y);
            a1.z = fminf(a1.z, b1.z); a1.w = fminf(a1.w, b1.w);
        }
        float contrib = ((a0.x + a0.y) + (a0.z + a0.w)
                       + (a1.x + a1.y) + (a1.z + a1.w)) * w;
        #pragma unroll
        for (int off = 16; off > 0; off >>= 1)
            contrib += __shfl_down_sync(mask, contrib, off);
        int lane = tid & 31, wid = tid >> 5;
        if (lane == 0) warp_sums[wid] = contrib;
        __syncthreads();
        if (tid == 0) {
            float v = 0.0f;
            #pragma unroll
            for (int i = 0; i < 8; i++) v += warp_sums[i];
            g_tilesum[tile] = v;
            __threadfence();
            int t = atomicAdd(&g_gtk, 1);
            role = (t == N_TILES - 1) ? 2 : 0;
        }
        __syncthreads();
    }

    // ---- Global finisher: sum tile sums, write out, reset tickets ----
    if (role == 2) {
        __threadfence();
        float v = (tid < N_TILES) ? g_tilesum[tid] : 0.0f;
        #pragma unroll
        for (int off = 16; off > 0; off >>= 1)
            v += __shfl_down_sync(mask, v, off);
        int lane = tid & 31, wid = tid >> 5;
        if (lane == 0) warp_sums[wid] = v;
        __syncthreads();
        if (tid < N_TILES) g_ttk[tid] = 0;        // reset for next replay
        if (tid == 0) {
            out[0] = warp_sums[0] + warp_sums[1];  // N_TILES=36 -> warps 0,1
            g_gtk = 0;
        }
    }
}

extern "C" void kernel_launch(void* const* d_in, const int* in_sizes, int n_in,
                              void* d_out, int out_size) {
    const float* state = (const float*)d_in[0];
    const float* model = (const float*)d_in[1];
    const float* vis   = (const float*)d_in[2];
    const float* tac   = (const float*)d_in[3];
    const float* pps   = (const float*)d_in[4];
    const float* dt    = (const float*)d_in[5];
    float* out = (float*)d_out;

    dim3 grid(N_TILES, CHUNKS);   // 36 x 16 = 576 blocks = exact 4/SM wave
    chamfer_kernel<<<grid, TPB>>>(state, pps, dt, model, vis, tac, out);
}